// round 1
// baseline (speedup 1.0000x reference)
#include <cuda_runtime.h>
#include <cuda_bf16.h>

// ---------------------------------------------------------------------------
// RtoVMainModel: conv1(3->6,5x5)+relu+pool2 ; conv2(6->16,5x5)+relu+pool2 ;
// flatten(400) ; LINEAR chains collapsed at runtime:
//   shapes head: Ws = sw3@sw2@sw1 (10x400), then shapes = relu(h)@sw4.T+sb4
//   experts:     We[e] = ew4[e]@ew3[e]@ew2[e]@ew1[e] (6x400)
// routing: pred=argmax(shapes); last[c]=max b with WIDTHS[pred[b]]>c (atomicMax)
// out[b][c] = covered(c) ? dot(xf[b], We[e_j[c]][c]) + be : 0
// d_out layout: [shapes (B*4) | out (B*6)] float32
// ---------------------------------------------------------------------------

#define B_TOTAL 16384

// scratch (device globals: no allocation allowed)
__device__ float g_T1[5 * 84 * 400];   // chain, W2@W1
__device__ float g_T2[5 * 10 * 400];   // chain, W3@W2@W1  (chain 0 = shapes = Ws)
__device__ float g_b3[5 * 10];         // collapsed bias through layer 3
__device__ float g_We[4 * 6 * 400];    // expert collapsed weights
__device__ float g_be[4 * 6];          // expert collapsed bias
__device__ float g_xf[B_TOTAL * 400];  // flattened conv features
__device__ int   g_last[6];            // packed (b<<2)|pred per column

// ---------------------------------------------------------------------------
__global__ void k_init() {
    if (threadIdx.x < 6) g_last[threadIdx.x] = -1;
}

// T1[chain] = W2 @ W1   (84 x 400), chain 0 = shapes, 1..4 = experts
__global__ void k_collapse1(const float* __restrict__ sw1, const float* __restrict__ sw2,
                            const float* __restrict__ ew1, const float* __restrict__ ew2) {
    int blk = blockIdx.x;
    int chain = blk / 84, row = blk % 84;
    const float* W2row = (chain == 0) ? (sw2 + row * 120)
                                      : (ew2 + ((chain - 1) * 84 + row) * 120);
    const float* W1 = (chain == 0) ? sw1 : (ew1 + (chain - 1) * 120 * 400);
    float acc[4] = {0.f, 0.f, 0.f, 0.f};
    for (int k = 0; k < 120; k++) {
        float w = W2row[k];
        const float* w1r = W1 + k * 400;
#pragma unroll
        for (int i = 0; i < 4; i++) {
            int j = threadIdx.x + i * 128;
            if (j < 400) acc[i] = fmaf(w, w1r[j], acc[i]);
        }
    }
    float* out = g_T1 + (chain * 84 + row) * 400;
#pragma unroll
    for (int i = 0; i < 4; i++) {
        int j = threadIdx.x + i * 128;
        if (j < 400) out[j] = acc[i];
    }
}

// collapsed biases: b2' = W2@b1+b2 ; b3' = W3@b2'+b3
__global__ void k_collapse_bias(const float* __restrict__ sb1, const float* __restrict__ sb2,
                                const float* __restrict__ sb3, const float* __restrict__ sw2,
                                const float* __restrict__ sw3,
                                const float* __restrict__ eb1, const float* __restrict__ eb2,
                                const float* __restrict__ eb3, const float* __restrict__ ew2,
                                const float* __restrict__ ew3) {
    int chain = blockIdx.x;
    const float* b1 = chain ? (eb1 + (chain - 1) * 120) : sb1;
    const float* b2 = chain ? (eb2 + (chain - 1) * 84) : sb2;
    const float* b3 = chain ? (eb3 + (chain - 1) * 10) : sb3;
    const float* W2 = chain ? (ew2 + (chain - 1) * 84 * 120) : sw2;
    const float* W3 = chain ? (ew3 + (chain - 1) * 10 * 84) : sw3;
    __shared__ float b2p[84];
    int tid = threadIdx.x;
    if (tid < 84) {
        float s = b2[tid];
        const float* r = W2 + tid * 120;
        for (int k = 0; k < 120; k++) s = fmaf(r[k], b1[k], s);
        b2p[tid] = s;
    }
    __syncthreads();
    if (tid < 10) {
        float s = b3[tid];
        const float* r = W3 + tid * 84;
        for (int k = 0; k < 84; k++) s = fmaf(r[k], b2p[k], s);
        g_b3[chain * 10 + tid] = s;
    }
}

// T2[chain] = W3 @ T1[chain]  (10 x 400)
__global__ void k_collapse2(const float* __restrict__ sw3, const float* __restrict__ ew3) {
    int chain = blockIdx.x / 10, row = blockIdx.x % 10;
    const float* W3row = (chain == 0) ? (sw3 + row * 84)
                                      : (ew3 + ((chain - 1) * 10 + row) * 84);
    const float* T1 = g_T1 + chain * 84 * 400;
    float acc[4] = {0.f, 0.f, 0.f, 0.f};
    for (int k = 0; k < 84; k++) {
        float w = W3row[k];
        const float* t = T1 + k * 400;
#pragma unroll
        for (int i = 0; i < 4; i++) {
            int j = threadIdx.x + i * 128;
            if (j < 400) acc[i] = fmaf(w, t[j], acc[i]);
        }
    }
    float* out = g_T2 + (chain * 10 + row) * 400;
#pragma unroll
    for (int i = 0; i < 4; i++) {
        int j = threadIdx.x + i * 128;
        if (j < 400) out[j] = acc[i];
    }
}

// We[e] = ew4[e] @ T2[1+e]  (6 x 400), be[e] = ew4[e]@b3'[1+e] + eb4[e]
__global__ void k_collapse3(const float* __restrict__ ew4, const float* __restrict__ eb4) {
    int e = blockIdx.x;
    int tid = threadIdx.x;
    __shared__ float w4[60];
    __shared__ float b3s[10];
    if (tid < 60) w4[tid] = ew4[e * 60 + tid];
    if (tid < 10) b3s[tid] = g_b3[(1 + e) * 10 + tid];
    __syncthreads();
    for (int idx = tid; idx < 2400; idx += 256) {
        int o = idx / 400, j = idx - o * 400;
        float s = 0.f;
#pragma unroll
        for (int k = 0; k < 10; k++)
            s = fmaf(w4[o * 10 + k], g_T2[((1 + e) * 10 + k) * 400 + j], s);
        g_We[e * 2400 + idx] = s;
    }
    if (tid < 6) {
        float s = eb4[e * 6 + tid];
#pragma unroll
        for (int k = 0; k < 10; k++) s = fmaf(w4[tid * 10 + k], b3s[k], s);
        g_be[e * 6 + tid] = s;
    }
}

// ---------------------------------------------------------------------------
// Main fused kernel: one block per image.
// conv1+pool -> conv2+pool (all in SMEM) -> xf -> h=Ws@xf+bs ->
// shapes=relu(h)@sw4.T+sb4 -> argmax -> atomicMax routing
// ---------------------------------------------------------------------------
__global__ void __launch_bounds__(256, 3)
k_main(const float* __restrict__ x,
       const float* __restrict__ c1w, const float* __restrict__ c1b,
       const float* __restrict__ c2w, const float* __restrict__ c2b,
       const float* __restrict__ sw4, const float* __restrict__ sb4,
       float* __restrict__ out) {
    __shared__ float xs[3072];     // 3 x 32 x 32
    __shared__ float w1s[456];     // 450 w + 6 b
    __shared__ float w2s[2416];    // 2400 w + 16 b
    __shared__ float y1s[1176];    // 6 x 14 x 14
    __shared__ float xfs[400];     // 16 x 5 x 5
    __shared__ float hs[10];
    __shared__ float shp[4];

    int b = blockIdx.x, tid = threadIdx.x;
    const float* xim = x + b * 3072;
    for (int i = tid; i < 768; i += 256)
        ((float4*)xs)[i] = ((const float4*)xim)[i];
    for (int i = tid; i < 450; i += 256) w1s[i] = c1w[i];
    if (tid < 6) w1s[450 + tid] = c1b[tid];
    for (int i = tid; i < 2400; i += 256) w2s[i] = c2w[i];
    if (tid < 16) w2s[2400 + tid] = c2b[tid];
    __syncthreads();

    // conv1 + relu + pool -> y1s (6,14,14)
    for (int idx = tid; idx < 1176; idx += 256) {
        int c = idx / 196, rem = idx - c * 196;
        int py = rem / 14, px = rem - py * 14;
        float bv = w1s[450 + c];
        float a00 = bv, a01 = bv, a10 = bv, a11 = bv;
        const float* wc = w1s + c * 75;
#pragma unroll
        for (int ic = 0; ic < 3; ic++) {
            const float* xp = xs + ic * 1024 + py * 64 + px * 2;
            const float* wp = wc + ic * 25;
#pragma unroll
            for (int ky = 0; ky < 5; ky++) {
                const float* xr = xp + ky * 32;
#pragma unroll
                for (int kx = 0; kx < 5; kx++) {
                    float w = wp[ky * 5 + kx];
                    a00 = fmaf(w, xr[kx], a00);
                    a01 = fmaf(w, xr[kx + 1], a01);
                    a10 = fmaf(w, xr[32 + kx], a10);
                    a11 = fmaf(w, xr[33 + kx], a11);
                }
            }
        }
        y1s[idx] = fmaxf(fmaxf(fmaxf(a00, a01), fmaxf(a10, a11)), 0.f);
    }
    __syncthreads();

    // conv2 + relu + pool -> xfs (16,5,5) = 400
    for (int idx = tid; idx < 400; idx += 256) {
        int c = idx / 25, rem = idx - c * 25;
        int py = rem / 5, px = rem - py * 5;
        float bv = w2s[2400 + c];
        float a00 = bv, a01 = bv, a10 = bv, a11 = bv;
        const float* wc = w2s + c * 150;
        for (int ic = 0; ic < 6; ic++) {
            const float* xp = y1s + ic * 196 + py * 28 + px * 2;
            const float* wp = wc + ic * 25;
#pragma unroll
            for (int ky = 0; ky < 5; ky++) {
                const float* xr = xp + ky * 14;
#pragma unroll
                for (int kx = 0; kx < 5; kx++) {
                    float w = wp[ky * 5 + kx];
                    a00 = fmaf(w, xr[kx], a00);
                    a01 = fmaf(w, xr[kx + 1], a01);
                    a10 = fmaf(w, xr[14 + kx], a10);
                    a11 = fmaf(w, xr[15 + kx], a11);
                }
            }
        }
        float v = fmaxf(fmaxf(fmaxf(a00, a01), fmaxf(a10, a11)), 0.f);
        xfs[idx] = v;
        g_xf[b * 400 + idx] = v;
    }
    __syncthreads();

    // h = Ws @ xf + bs  (10 outputs, 16 lanes each)
    if (tid < 160) {
        int o = tid >> 4, l = tid & 15;
        const float* wr = g_T2 + o * 400;  // chain 0 = shapes
        float s = 0.f;
        for (int j = l; j < 400; j += 16) s = fmaf(wr[j], xfs[j], s);
        s += __shfl_down_sync(0xffffffffu, s, 8, 16);
        s += __shfl_down_sync(0xffffffffu, s, 4, 16);
        s += __shfl_down_sync(0xffffffffu, s, 2, 16);
        s += __shfl_down_sync(0xffffffffu, s, 1, 16);
        if (l == 0) hs[o] = s + g_b3[o];
    }
    __syncthreads();

    // shapes = relu(h) @ sw4.T + sb4
    if (tid < 4) {
        float s = sb4[tid];
#pragma unroll
        for (int o = 0; o < 10; o++)
            s = fmaf(fmaxf(hs[o], 0.f), sw4[tid * 10 + o], s);
        shp[tid] = s;
        out[b * 4 + tid] = s;
    }
    __syncthreads();

    // routing: argmax (first-max tiebreak), atomicMax packed (b<<2)|pred
    if (tid == 0) {
        int pred = 0;
        float best = shp[0];
#pragma unroll
        for (int k = 1; k < 4; k++)
            if (shp[k] > best) { best = shp[k]; pred = k; }
        const int widths[4] = {3, 5, 6, 5};
        int w = widths[pred];
        int val = (b << 2) | pred;
        for (int c = 0; c < w; c++) atomicMax(&g_last[c], val);
    }
}

// ---------------------------------------------------------------------------
// out[b][c] = covered(c) ? dot(xf[b], We[e_j[c]][c]) + be : 0
// 32 rows per block, 8 threads per row (cols 0..5 active, 6..7 idle)
// ---------------------------------------------------------------------------
__global__ void __launch_bounds__(256)
k_out(float* __restrict__ out) {
    __shared__ float wsel[6 * 400];
    __shared__ float bsel[6];
    int tid = threadIdx.x;
    for (int idx = tid; idx < 2400; idx += 256) {
        int c = idx / 400;
        int p = g_last[c];
        wsel[idx] = (p >= 0) ? g_We[(p & 3) * 2400 + idx] : 0.f;
    }
    if (tid < 6) {
        int p = g_last[tid];
        bsel[tid] = (p >= 0) ? g_be[(p & 3) * 6 + tid] : 0.f;
    }
    __syncthreads();
    int c = tid & 7, r = tid >> 3;
    int b = blockIdx.x * 32 + r;
    if (c < 6) {
        const float* xfp = g_xf + b * 400;
        const float* wr = wsel + c * 400;
        float s = bsel[c];
        for (int j = 0; j < 400; j++) s = fmaf(xfp[j], wr[j], s);
        out[B_TOTAL * 4 + b * 6 + c] = s;
    }
}

// ---------------------------------------------------------------------------
extern "C" void kernel_launch(void* const* d_in, const int* in_sizes, int n_in,
                              void* d_out, int out_size) {
    const float* x    = (const float*)d_in[0];
    const float* c1w  = (const float*)d_in[1];
    const float* c1b  = (const float*)d_in[2];
    const float* c2w  = (const float*)d_in[3];
    const float* c2b  = (const float*)d_in[4];
    const float* sw1  = (const float*)d_in[5];
    const float* sb1  = (const float*)d_in[6];
    const float* sw2  = (const float*)d_in[7];
    const float* sb2  = (const float*)d_in[8];
    const float* sw3  = (const float*)d_in[9];
    const float* sb3  = (const float*)d_in[10];
    const float* sw4  = (const float*)d_in[11];
    const float* sb4  = (const float*)d_in[12];
    const float* ew1  = (const float*)d_in[13];
    const float* eb1  = (const float*)d_in[14];
    const float* ew2  = (const float*)d_in[15];
    const float* eb2  = (const float*)d_in[16];
    const float* ew3  = (const float*)d_in[17];
    const float* eb3  = (const float*)d_in[18];
    const float* ew4  = (const float*)d_in[19];
    const float* eb4  = (const float*)d_in[20];
    float* out = (float*)d_out;

    k_init<<<1, 32>>>();
    k_collapse1<<<420, 128>>>(sw1, sw2, ew1, ew2);
    k_collapse_bias<<<5, 128>>>(sb1, sb2, sb3, sw2, sw3, eb1, eb2, eb3, ew2, ew3);
    k_collapse2<<<50, 128>>>(sw3, ew3);
    k_collapse3<<<4, 256>>>(ew4, eb4);
    k_main<<<B_TOTAL, 256>>>(x, c1w, c1b, c2w, c2b, sw4, sb4, out);
    k_out<<<B_TOTAL / 32, 256>>>(out);
}

// round 2
// speedup vs baseline: 1.5857x; 1.5857x over previous
#include <cuda_runtime.h>
#include <cuda_bf16.h>

// ---------------------------------------------------------------------------
// RtoVMainModel: conv1(3->6,5x5)+relu+pool2 ; conv2(6->16,5x5)+relu+pool2 ;
// flatten(400) ; LINEAR chains collapsed at runtime (Ws=sw3@sw2@sw1 etc.)
// Main kernel: packed f32x2 FMA row-blocked convs, all-in-smem per image.
// d_out layout: [shapes (B*4) | out (B*6)] float32
// ---------------------------------------------------------------------------

#define B_TOTAL 16384
typedef unsigned long long u64;

__device__ __forceinline__ u64 pk(float lo, float hi) {
    u64 r; asm("mov.b64 %0, {%1, %2};" : "=l"(r) : "f"(lo), "f"(hi)); return r;
}
__device__ __forceinline__ void upk(u64 p, float& lo, float& hi) {
    asm("mov.b64 {%0, %1}, %2;" : "=f"(lo), "=f"(hi) : "l"(p));
}
__device__ __forceinline__ u64 fma2(u64 a, u64 b, u64 c) {
    u64 d; asm("fma.rn.f32x2 %0, %1, %2, %3;" : "=l"(d) : "l"(a), "l"(b), "l"(c)); return d;
}

// scratch (device globals: no allocation allowed)
__device__ float g_T1[5 * 84 * 400];
__device__ float g_T2[5 * 10 * 400];   // chain 0 = shapes head collapsed (10x400)
__device__ float g_b3[5 * 10];
__device__ float g_We[4 * 6 * 400];
__device__ float g_be[4 * 6];
__device__ float g_xf[B_TOTAL * 400];
__device__ int   g_last[6];

// ---------------------------------------------------------------------------
__global__ void k_init() {
    if (threadIdx.x < 6) g_last[threadIdx.x] = -1;
}

__global__ void k_collapse1(const float* __restrict__ sw1, const float* __restrict__ sw2,
                            const float* __restrict__ ew1, const float* __restrict__ ew2) {
    int blk = blockIdx.x;
    int chain = blk / 84, row = blk % 84;
    const float* W2row = (chain == 0) ? (sw2 + row * 120)
                                      : (ew2 + ((chain - 1) * 84 + row) * 120);
    const float* W1 = (chain == 0) ? sw1 : (ew1 + (chain - 1) * 120 * 400);
    float acc[4] = {0.f, 0.f, 0.f, 0.f};
    for (int k = 0; k < 120; k++) {
        float w = W2row[k];
        const float* w1r = W1 + k * 400;
#pragma unroll
        for (int i = 0; i < 4; i++) {
            int j = threadIdx.x + i * 128;
            if (j < 400) acc[i] = fmaf(w, w1r[j], acc[i]);
        }
    }
    float* o = g_T1 + (chain * 84 + row) * 400;
#pragma unroll
    for (int i = 0; i < 4; i++) {
        int j = threadIdx.x + i * 128;
        if (j < 400) o[j] = acc[i];
    }
}

__global__ void k_collapse_bias(const float* __restrict__ sb1, const float* __restrict__ sb2,
                                const float* __restrict__ sb3, const float* __restrict__ sw2,
                                const float* __restrict__ sw3,
                                const float* __restrict__ eb1, const float* __restrict__ eb2,
                                const float* __restrict__ eb3, const float* __restrict__ ew2,
                                const float* __restrict__ ew3) {
    int chain = blockIdx.x;
    const float* b1 = chain ? (eb1 + (chain - 1) * 120) : sb1;
    const float* b2 = chain ? (eb2 + (chain - 1) * 84) : sb2;
    const float* b3 = chain ? (eb3 + (chain - 1) * 10) : sb3;
    const float* W2 = chain ? (ew2 + (chain - 1) * 84 * 120) : sw2;
    const float* W3 = chain ? (ew3 + (chain - 1) * 10 * 84) : sw3;
    __shared__ float b2p[84];
    int tid = threadIdx.x;
    if (tid < 84) {
        float s = b2[tid];
        const float* r = W2 + tid * 120;
        for (int k = 0; k < 120; k++) s = fmaf(r[k], b1[k], s);
        b2p[tid] = s;
    }
    __syncthreads();
    if (tid < 10) {
        float s = b3[tid];
        const float* r = W3 + tid * 84;
        for (int k = 0; k < 84; k++) s = fmaf(r[k], b2p[k], s);
        g_b3[chain * 10 + tid] = s;
    }
}

__global__ void k_collapse2(const float* __restrict__ sw3, const float* __restrict__ ew3) {
    int chain = blockIdx.x / 10, row = blockIdx.x % 10;
    const float* W3row = (chain == 0) ? (sw3 + row * 84)
                                      : (ew3 + ((chain - 1) * 10 + row) * 84);
    const float* T1 = g_T1 + chain * 84 * 400;
    float acc[4] = {0.f, 0.f, 0.f, 0.f};
    for (int k = 0; k < 84; k++) {
        float w = W3row[k];
        const float* t = T1 + k * 400;
#pragma unroll
        for (int i = 0; i < 4; i++) {
            int j = threadIdx.x + i * 128;
            if (j < 400) acc[i] = fmaf(w, t[j], acc[i]);
        }
    }
    float* o = g_T2 + (chain * 10 + row) * 400;
#pragma unroll
    for (int i = 0; i < 4; i++) {
        int j = threadIdx.x + i * 128;
        if (j < 400) o[j] = acc[i];
    }
}

__global__ void k_collapse3(const float* __restrict__ ew4, const float* __restrict__ eb4) {
    int e = blockIdx.x;
    int tid = threadIdx.x;
    __shared__ float w4[60];
    __shared__ float b3s[10];
    if (tid < 60) w4[tid] = ew4[e * 60 + tid];
    if (tid < 10) b3s[tid] = g_b3[(1 + e) * 10 + tid];
    __syncthreads();
    for (int idx = tid; idx < 2400; idx += 256) {
        int o = idx / 400, j = idx - o * 400;
        float s = 0.f;
#pragma unroll
        for (int k = 0; k < 10; k++)
            s = fmaf(w4[o * 10 + k], g_T2[((1 + e) * 10 + k) * 400 + j], s);
        g_We[e * 2400 + idx] = s;
    }
    if (tid < 6) {
        float s = eb4[e * 6 + tid];
#pragma unroll
        for (int k = 0; k < 10; k++) s = fmaf(w4[tid * 10 + k], b3s[k], s);
        g_be[e * 6 + tid] = s;
    }
}

// ---------------------------------------------------------------------------
// Main fused kernel: one block (192 threads) per image.
// ---------------------------------------------------------------------------
__global__ void __launch_bounds__(192, 3)
k_main(const float* __restrict__ x,
       const float* __restrict__ c1w, const float* __restrict__ c1b,
       const float* __restrict__ c2w, const float* __restrict__ c2b,
       const float* __restrict__ sw4, const float* __restrict__ sb4,
       float* __restrict__ out) {
    __shared__ __align__(16) float  s_x[3 * 32 * 36];   // padded rows; aliased s_part later
    __shared__ __align__(16) float  s_y1[6 * 14 * 20];  // pool1 out, padded rows
    __shared__ __align__(16) float2 s_w1p[450];         // {w,w} pairs
    __shared__ __align__(16) float2 s_w2p[2400];
    __shared__ float s_b1[6], s_b2[16];
    __shared__ __align__(16) float s_xf[400];
    __shared__ float hs[10], shp[4];

    int b = blockIdx.x, tid = threadIdx.x;

    // ---- load phase ----
    const float4* xg = (const float4*)(x + b * 3072);
    for (int g = tid; g < 768; g += 192) {
        float4 v = xg[g];
        int gr = g >> 3, c4 = g & 7;
        *(float4*)(s_x + gr * 36 + c4 * 4) = v;
    }
    for (int i = tid; i < 450; i += 192)  { float w = c1w[i]; s_w1p[i] = make_float2(w, w); }
    for (int i = tid; i < 2400; i += 192) { float w = c2w[i]; s_w2p[i] = make_float2(w, w); }
    if (tid < 6)  s_b1[tid] = c1b[tid];
    if (tid < 16) s_b2[tid] = c2b[tid];
    __syncthreads();

    // ---- conv1 + relu + pool: task = (ch, pooled row, half) = 168 tasks ----
    if (tid < 168) {
        int ch = tid / 28, rem = tid % 28, py = rem >> 1, h = rem & 1;
        u64 acc0[7], acc1[7];
#pragma unroll
        for (int j = 0; j < 7; j++) { acc0[j] = 0ull; acc1[j] = 0ull; }
        const float* xbase = s_x + (2 * py) * 36 + 14 * h;
#pragma unroll 1
        for (int ic = 0; ic < 3; ic++) {
            const float2* wb = s_w1p + (ch * 3 + ic) * 25;
            u64 wv[5][5];
#pragma unroll
            for (int xr = 0; xr < 6; xr++) {
                const u64* rp = (const u64*)(xbase + ic * (32 * 36) + xr * 36);
                u64 pe[9]; float xl[9], xh[9];
#pragma unroll
                for (int m = 0; m < 9; m++) { pe[m] = rp[m]; upk(pe[m], xl[m], xh[m]); }
                u64 po[8];
#pragma unroll
                for (int m = 0; m < 8; m++) po[m] = pk(xh[m], xl[m + 1]);
                if (xr < 5) {
#pragma unroll
                    for (int k = 0; k < 5; k++) wv[xr][k] = *(const u64*)&wb[xr * 5 + k];
#pragma unroll
                    for (int kx = 0; kx < 5; kx++) {
                        u64 w = wv[xr][kx];
#pragma unroll
                        for (int j = 0; j < 7; j++)
                            acc0[j] = fma2(w, (kx & 1) ? po[j + (kx >> 1)] : pe[j + (kx >> 1)], acc0[j]);
                    }
                }
                if (xr >= 1) {
#pragma unroll
                    for (int kx = 0; kx < 5; kx++) {
                        u64 w = wv[xr - 1][kx];
#pragma unroll
                        for (int j = 0; j < 7; j++)
                            acc1[j] = fma2(w, (kx & 1) ? po[j + (kx >> 1)] : pe[j + (kx >> 1)], acc1[j]);
                    }
                }
            }
        }
        float bv = s_b1[ch];
        float* yrow = s_y1 + (ch * 14 + py) * 20 + 7 * h;
#pragma unroll
        for (int j = 0; j < 7; j++) {
            float a0, a1, c0, c1;
            upk(acc0[j], a0, a1); upk(acc1[j], c0, c1);
            float m = fmaxf(fmaxf(a0, a1), fmaxf(c0, c1)) + bv;
            yrow[j] = fmaxf(m, 0.f);
        }
    }
    __syncthreads();

    // ---- conv2: task = (icg, ch, pooled row) = 160 tasks, 2-way K split ----
    float* s_part = s_x;  // alias: x is dead
    int icg = tid / 80;
    int r2 = tid % 80, ch2 = r2 / 5, py2 = r2 % 5;
    u64 b0[5], b1[5];
    if (tid < 160) {
#pragma unroll
        for (int j = 0; j < 5; j++) { b0[j] = 0ull; b1[j] = 0ull; }
#pragma unroll 1
        for (int ici = 0; ici < 3; ici++) {
            int ic = icg * 3 + ici;
            const float2* wb = s_w2p + (ch2 * 6 + ic) * 25;
            u64 wv[5][5];
#pragma unroll
            for (int xr = 0; xr < 6; xr++) {
                const u64* rp = (const u64*)(s_y1 + (ic * 14 + 2 * py2 + xr) * 20);
                u64 pe[7]; float xl[7], xh[7];
#pragma unroll
                for (int m = 0; m < 7; m++) { pe[m] = rp[m]; upk(pe[m], xl[m], xh[m]); }
                u64 po[6];
#pragma unroll
                for (int m = 0; m < 6; m++) po[m] = pk(xh[m], xl[m + 1]);
                if (xr < 5) {
#pragma unroll
                    for (int k = 0; k < 5; k++) wv[xr][k] = *(const u64*)&wb[xr * 5 + k];
#pragma unroll
                    for (int kx = 0; kx < 5; kx++) {
                        u64 w = wv[xr][kx];
#pragma unroll
                        for (int j = 0; j < 5; j++)
                            b0[j] = fma2(w, (kx & 1) ? po[j + (kx >> 1)] : pe[j + (kx >> 1)], b0[j]);
                    }
                }
                if (xr >= 1) {
#pragma unroll
                    for (int kx = 0; kx < 5; kx++) {
                        u64 w = wv[xr - 1][kx];
#pragma unroll
                        for (int j = 0; j < 5; j++)
                            b1[j] = fma2(w, (kx & 1) ? po[j + (kx >> 1)] : pe[j + (kx >> 1)], b1[j]);
                    }
                }
            }
        }
        if (icg == 1) {
            float* pp = s_part + r2 * 20;
#pragma unroll
            for (int j = 0; j < 5; j++) {
                float a, bq;
                upk(b0[j], a, bq); pp[2 * j] = a; pp[2 * j + 1] = bq;
                upk(b1[j], a, bq); pp[10 + 2 * j] = a; pp[10 + 2 * j + 1] = bq;
            }
        }
    }
    __syncthreads();

    // combine halves + pool + relu -> xf
    if (tid < 80) {
        float bv = s_b2[ch2];
        const float* pp = s_part + r2 * 20;
        float* xfp = s_xf + ch2 * 25 + py2 * 5;
        float* gxf = g_xf + (size_t)b * 400 + ch2 * 25 + py2 * 5;
#pragma unroll
        for (int j = 0; j < 5; j++) {
            float a0, a1, c0, c1;
            upk(b0[j], a0, a1); upk(b1[j], c0, c1);
            float v = fmaxf(fmaxf(a0 + pp[2 * j], a1 + pp[2 * j + 1]),
                            fmaxf(c0 + pp[10 + 2 * j], c1 + pp[10 + 2 * j + 1])) + bv;
            v = fmaxf(v, 0.f);
            xfp[j] = v; gxf[j] = v;
        }
    }
    __syncthreads();

    // ---- h = Ws @ xf + bs (10 outputs x 16 lanes) ----
    if (tid < 160) {
        int o = tid >> 4, l = tid & 15;
        const float* wr = g_T2 + o * 400;
        float s = 0.f;
        for (int j = l; j < 400; j += 16) s = fmaf(wr[j], s_xf[j], s);
        s += __shfl_down_sync(0xffffffffu, s, 8, 16);
        s += __shfl_down_sync(0xffffffffu, s, 4, 16);
        s += __shfl_down_sync(0xffffffffu, s, 2, 16);
        s += __shfl_down_sync(0xffffffffu, s, 1, 16);
        if (l == 0) hs[o] = s + g_b3[o];
    }
    __syncthreads();

    // shapes = relu(h) @ sw4.T + sb4
    if (tid < 4) {
        float s = sb4[tid];
#pragma unroll
        for (int o = 0; o < 10; o++)
            s = fmaf(fmaxf(hs[o], 0.f), sw4[tid * 10 + o], s);
        shp[tid] = s;
        out[b * 4 + tid] = s;
    }
    __syncthreads();

    // routing
    if (tid == 0) {
        int pred = 0;
        float best = shp[0];
#pragma unroll
        for (int k = 1; k < 4; k++)
            if (shp[k] > best) { best = shp[k]; pred = k; }
        const int widths[4] = {3, 5, 6, 5};
        int w = widths[pred];
        int val = (b << 2) | pred;
        for (int c = 0; c < w; c++) atomicMax(&g_last[c], val);
    }
}

// ---------------------------------------------------------------------------
__global__ void __launch_bounds__(256)
k_out(float* __restrict__ out) {
    __shared__ float wsel[6 * 400];
    __shared__ float bsel[6];
    int tid = threadIdx.x;
    for (int idx = tid; idx < 2400; idx += 256) {
        int c = idx / 400;
        int p = g_last[c];
        wsel[idx] = (p >= 0) ? g_We[(p & 3) * 2400 + idx] : 0.f;
    }
    if (tid < 6) {
        int p = g_last[tid];
        bsel[tid] = (p >= 0) ? g_be[(p & 3) * 6 + tid] : 0.f;
    }
    __syncthreads();
    int c = tid & 7, r = tid >> 3;
    int b = blockIdx.x * 32 + r;
    if (c < 6) {
        const float* xfp = g_xf + (size_t)b * 400;
        const float* wr = wsel + c * 400;
        float s = bsel[c];
        for (int j = 0; j < 400; j++) s = fmaf(xfp[j], wr[j], s);
        out[B_TOTAL * 4 + b * 6 + c] = s;
    }
}

// ---------------------------------------------------------------------------
extern "C" void kernel_launch(void* const* d_in, const int* in_sizes, int n_in,
                              void* d_out, int out_size) {
    const float* x    = (const float*)d_in[0];
    const float* c1w  = (const float*)d_in[1];
    const float* c1b  = (const float*)d_in[2];
    const float* c2w  = (const float*)d_in[3];
    const float* c2b  = (const float*)d_in[4];
    const float* sw1  = (const float*)d_in[5];
    const float* sb1  = (const float*)d_in[6];
    const float* sw2  = (const float*)d_in[7];
    const float* sb2  = (const float*)d_in[8];
    const float* sw3  = (const float*)d_in[9];
    const float* sb3  = (const float*)d_in[10];
    const float* sw4  = (const float*)d_in[11];
    const float* sb4  = (const float*)d_in[12];
    const float* ew1  = (const float*)d_in[13];
    const float* eb1  = (const float*)d_in[14];
    const float* ew2  = (const float*)d_in[15];
    const float* eb2  = (const float*)d_in[16];
    const float* ew3  = (const float*)d_in[17];
    const float* eb3  = (const float*)d_in[18];
    const float* ew4  = (const float*)d_in[19];
    const float* eb4  = (const float*)d_in[20];
    float* out = (float*)d_out;

    k_init<<<1, 32>>>();
    k_collapse1<<<420, 128>>>(sw1, sw2, ew1, ew2);
    k_collapse_bias<<<5, 128>>>(sb1, sb2, sb3, sw2, sw3, eb1, eb2, eb3, ew2, ew3);
    k_collapse2<<<50, 128>>>(sw3, ew3);
    k_collapse3<<<4, 256>>>(ew4, eb4);
    k_main<<<B_TOTAL, 192>>>(x, c1w, c1b, c2w, c2b, sw4, sb4, out);
    k_out<<<B_TOTAL / 32, 256>>>(out);
}